// round 13
// baseline (speedup 1.0000x reference)
#include <cuda_runtime.h>
#include <cuda_fp16.h>
#include <cstdint>
#include <cstddef>

// Problem constants (fixed for this problem; M derived at launch)
#define KDIM 4096
#define NDIM 11008
#define MMAX 8192
#define BM 128
#define BN 128
#define BK 64
#define STAGES 3
#define KT (KDIM / BK)        // 64
#define SA_STRIDE 72          // 64+8 halves -> 144B row stride (conflict-free ldmatrix)
#define SB_STRIDE 136         // 128+8 halves -> 272B row stride (R7-proven)
#define A_STG (BM * SA_STRIDE)
#define B_STG (BK * SB_STRIDE)
#define DQ_BLOCKS ((NDIM / 64) * (KDIM / 256))   // 172*16 = 2752

// fp16 scratch: dequantized weights (scale folded), K-major [K][N]; fp16 copy of x.
static __device__ __half g_W[(size_t)KDIM * NDIM];   // 90.2 MB
static __device__ __half g_X[(size_t)MMAX * KDIM];   // 67.1 MB

// ---------------------------------------------------------------------------
// Phase 1 (fused): blocks [0, DQ_BLOCKS) dequantize packed ternary -> g_W;
// blocks [DQ_BLOCKS, ...) convert x f32->f16 -> g_X.
// Dequant math (proven bit-identical): 16-entry half2 LUT of exact (code-1)
// in {-1,0,+1}; hmul2 by fp16 scale gives {-s,0,+s} exactly.
// ---------------------------------------------------------------------------
__global__ __launch_bounds__(256) void prep_kernel(
    const float* __restrict__ x, const int32_t* __restrict__ pw,
    const float* __restrict__ scales, long long nx)
{
    __shared__ __half2 lut[16];
    __shared__ __half sw[256][72];   // row stride 144B (16B-aligned)
    const int t = threadIdx.x;

    if (blockIdx.x >= DQ_BLOCKS) {
        long long i = ((long long)(blockIdx.x - DQ_BLOCKS) * 256 + t) * 8;
        if (i + 8 <= nx) {
            float4 a = *reinterpret_cast<const float4*>(x + i);
            float4 b = *reinterpret_cast<const float4*>(x + i + 4);
            __half2 h[4];
            h[0] = __floats2half2_rn(a.x, a.y);
            h[1] = __floats2half2_rn(a.z, a.w);
            h[2] = __floats2half2_rn(b.x, b.y);
            h[3] = __floats2half2_rn(b.z, b.w);
            *reinterpret_cast<uint4*>(&g_X[i]) = *reinterpret_cast<uint4*>(h);
        }
        return;
    }

    const int n0  = (blockIdx.x % (NDIM / 64)) * 64;
    const int kp0 = (blockIdx.x / (NDIM / 64)) * 16;
    const int nl  = (t & 31) * 2;
    const int r0  = t >> 5;

    if (t < 16)
        lut[t] = __halves2half2(__int2half_rn((t & 3) - 1),
                                __int2half_rn((t >> 2) - 1));
    __syncthreads();

#pragma unroll
    for (int rr = r0; rr < 16; rr += 8) {
        const int kp = kp0 + rr;
        const int n  = n0 + nl;
        const int2  vab = *reinterpret_cast<const int2*>(&pw[(size_t)kp * NDIM + n]);
        const uint32_t va = (uint32_t)vab.x;
        const uint32_t vb = (uint32_t)vab.y;
        const int g = kp >> 3;
        const float2 sf = *reinterpret_cast<const float2*>(&scales[(size_t)g * NDIM + n]);
        const __half2 s2 = __floats2half2_rn(sf.x, sf.y);

        const uint32_t w1 = (va & 0x33333333u) | ((vb & 0x33333333u) << 2);
        const uint32_t w2 = ((va >> 2) & 0x33333333u) | (((vb >> 2) & 0x33333333u) << 2);

        __half* row_base = &sw[rr * 16][0];
#pragma unroll
        for (int m = 0; m < 8; m++) {
            const __half2 he = __hmul2(lut[(w1 >> (4 * m)) & 0xFu], s2);
            const __half2 ho = __hmul2(lut[(w2 >> (4 * m)) & 0xFu], s2);
            *reinterpret_cast<__half2*>(row_base + (2 * m) * 72 + nl)     = he;
            *reinterpret_cast<__half2*>(row_base + (2 * m + 1) * 72 + nl) = ho;
        }
    }
    __syncthreads();

#pragma unroll
    for (int i = t; i < 2048; i += 256) {
        const int row = i >> 3, c = i & 7;
        *reinterpret_cast<uint4*>(&g_W[(size_t)(kp0 * 16 + row) * NDIM + n0 + c * 8]) =
            *reinterpret_cast<const uint4*>(&sw[row][c * 8]);
    }
}

// ---------------------------------------------------------------------------
// Phase 2: fp16 GEMM, fp32 acc. 128x128 tile, 3 stages, 2 CTAs/SM so one
// CTA's MMAs cover the other's sync bubbles. Single-buffered fragments
// (4 warps/SMSP hide LDSM latency). Regs capped at 128 by launch_bounds.
// C_f32 = float( half(acc) + half(bias) ), reference rounding order.
// ---------------------------------------------------------------------------
#define CP_ASYNC16(dst, src) \
    asm volatile("cp.async.cg.shared.global [%0], [%1], 16;\n" :: "r"(dst), "l"(src))

__global__ __launch_bounds__(256, 2) void gemm_kernel(
    const float* __restrict__ bias, float* __restrict__ C, int M)
{
    extern __shared__ __half smem[];
    __half* sA = smem;                      // [STAGES][BM][SA_STRIDE]
    __half* sB = smem + STAGES * A_STG;     // [STAGES][BK][SB_STRIDE]

    const int tiles_n = NDIM / BN;          // 86
    const int tiles_m = M / BM;             // 64

    // GROUP_M=16 rasterization for L2 reuse of B.
    const int pid = blockIdx.x;
    const int GROUPM = 16;
    const int per_group = GROUPM * tiles_n;
    const int gid = pid / per_group;
    const int first_m = gid * GROUPM;
    const int gsz = min(GROUPM, tiles_m - first_m);
    const int rr  = pid % per_group;
    const int m0 = (first_m + rr % gsz) * BM;
    const int n0 = (rr / gsz) * BN;

    const int tid  = threadIdx.x;
    const int lane = tid & 31;
    const int warp = tid >> 5;
    const int wr = warp & 1;     // 0..1 -> 64-row slice
    const int wc = warp >> 1;    // 0..3 -> 32-col slice

    float acc[4][4][4];
#pragma unroll
    for (int a = 0; a < 4; a++)
#pragma unroll
        for (int b = 0; b < 4; b++)
#pragma unroll
            for (int c = 0; c < 4; c++) acc[a][b][c] = 0.f;

    const uint32_t sA_base = (uint32_t)__cvta_generic_to_shared(sA);
    const uint32_t sB_base = (uint32_t)__cvta_generic_to_shared(sB);

    // gmem->smem 16B-chunk coordinates.
    const int a_row = tid >> 3;           // +32/iter (4 iters)
    const int a_c   = (tid & 7) * 8;
    const int b_row = tid >> 4;           // +16/iter (4 iters)
    const int b_c   = (tid & 15) * 8;

    const __half* Ag = g_X + (size_t)(m0 + a_row) * KDIM + a_c;
    const __half* Bg = g_W + (size_t)b_row * NDIM + n0 + b_c;

    auto load_A = [&](int stage, int kt) {
        uint32_t da = sA_base + (uint32_t)(stage * A_STG + a_row * SA_STRIDE + a_c) * 2;
        const __half* ga = Ag + kt * BK;
#pragma unroll
        for (int i = 0; i < 4; i++) {
            CP_ASYNC16(da, ga);
            da += 32 * SA_STRIDE * 2;
            ga += (size_t)32 * KDIM;
        }
    };
    auto load_B = [&](int stage, int kt) {
        uint32_t db = sB_base + (uint32_t)(stage * B_STG + b_row * SB_STRIDE + b_c) * 2;
        const __half* gb = Bg + (size_t)kt * BK * NDIM;
#pragma unroll
        for (int i = 0; i < 4; i++) {
            CP_ASYNC16(db, gb);
            db += 16 * SB_STRIDE * 2;
            gb += (size_t)16 * NDIM;
        }
    };

    // ldmatrix lane-address components (R7-proven mapping).
    const int lrow  = (lane & 7) + ((lane >> 3) & 1) * 8;
    const int acoff = ((lane >> 4) & 1) * 8;
    const int bkr   = (lane & 7) + ((lane >> 3) & 1) * 8;
    const int bnc   = wc * 32 + ((lane >> 4) & 1) * 8;

    uint32_t fa[4][4], fb[4][2];

    auto ldsm = [&](int stage, int ks) {
        const uint32_t pa = sA_base + (uint32_t)(stage * A_STG) * 2;
        const uint32_t pb = sB_base + (uint32_t)(stage * B_STG) * 2;
#pragma unroll
        for (int mi = 0; mi < 4; mi++) {
            const uint32_t addr = pa +
                (uint32_t)((wr * 64 + mi * 16 + lrow) * SA_STRIDE + ks * 16 + acoff) * 2;
            asm volatile("ldmatrix.sync.aligned.m8n8.x4.shared.b16 {%0,%1,%2,%3}, [%4];\n"
                : "=r"(fa[mi][0]), "=r"(fa[mi][1]), "=r"(fa[mi][2]), "=r"(fa[mi][3])
                : "r"(addr));
        }
#pragma unroll
        for (int ng = 0; ng < 2; ng++) {
            const uint32_t addr = pb +
                (uint32_t)((ks * 16 + bkr) * SB_STRIDE + bnc + ng * 16) * 2;
            uint32_t r0, r1, r2, r3;
            asm volatile("ldmatrix.sync.aligned.m8n8.x4.trans.shared.b16 {%0,%1,%2,%3}, [%4];\n"
                : "=r"(r0), "=r"(r1), "=r"(r2), "=r"(r3) : "r"(addr));
            fb[2 * ng][0] = r0;     fb[2 * ng][1] = r1;
            fb[2 * ng + 1][0] = r2; fb[2 * ng + 1][1] = r3;
        }
    };

    auto mma_all = [&]() {
#pragma unroll
        for (int mi = 0; mi < 4; mi++)
#pragma unroll
            for (int ni = 0; ni < 4; ni++) {
                asm volatile(
                    "mma.sync.aligned.m16n8k16.row.col.f32.f16.f16.f32 "
                    "{%0,%1,%2,%3}, {%4,%5,%6,%7}, {%8,%9}, {%0,%1,%2,%3};\n"
                    : "+f"(acc[mi][ni][0]), "+f"(acc[mi][ni][1]),
                      "+f"(acc[mi][ni][2]), "+f"(acc[mi][ni][3])
                    : "r"(fa[mi][0]), "r"(fa[mi][1]), "r"(fa[mi][2]), "r"(fa[mi][3]),
                      "r"(fb[ni][0]), "r"(fb[ni][1]));
            }
    };

    // Prologue: fill STAGES-1 stages.
#pragma unroll
    for (int s = 0; s < STAGES - 1; s++) {
        load_A(s, s);
        load_B(s, s);
        asm volatile("cp.async.commit_group;\n");
    }
    asm volatile("cp.async.wait_group %0;\n" :: "n"(STAGES - 2) : "memory");
    __syncthreads();

    int stage = 0, lstage = STAGES - 1;
    for (int kt = 0; kt < KT; kt++) {
        const int lkt = kt + STAGES - 1;
        const bool do_load = lkt < KT;
#pragma unroll
        for (int ks = 0; ks < 4; ks++) {
            if (ks == 0 && do_load) load_A(lstage, lkt);
            if (ks == 1 && do_load) load_B(lstage, lkt);
            if (ks == 2)
                asm volatile("cp.async.commit_group;\n");   // one group per kt
            ldsm(stage, ks);
            mma_all();
        }
        asm volatile("cp.async.wait_group %0;\n" :: "n"(STAGES - 2) : "memory");
        __syncthreads();
        stage  = (stage  + 1 == STAGES) ? 0 : stage + 1;
        lstage = (lstage + 1 == STAGES) ? 0 : lstage + 1;
    }

    // Epilogue: half(acc) + half(bias) in fp16 (reference rounding), widen to fp32.
#pragma unroll
    for (int mi = 0; mi < 4; mi++) {
        const int row = m0 + wr * 64 + mi * 16 + (lane >> 2);
#pragma unroll
        for (int ni = 0; ni < 4; ni++) {
            const int col = n0 + wc * 32 + ni * 8 + (lane & 3) * 2;
            const float2 bf32 = *reinterpret_cast<const float2*>(bias + col);
            const __half2 bv = __floats2half2_rn(bf32.x, bf32.y);
            __half2 v0 = __hadd2(__floats2half2_rn(acc[mi][ni][0], acc[mi][ni][1]), bv);
            __half2 v1 = __hadd2(__floats2half2_rn(acc[mi][ni][2], acc[mi][ni][3]), bv);
            float2 o0 = __half22float2(v0);
            float2 o1 = __half22float2(v1);
            *reinterpret_cast<float2*>(C + (size_t)row * NDIM + col) = o0;
            *reinterpret_cast<float2*>(C + (size_t)(row + 8) * NDIM + col) = o1;
        }
    }
}

// ---------------------------------------------------------------------------
extern "C" void kernel_launch(void* const* d_in, const int* in_sizes, int n_in,
                              void* d_out, int out_size) {
    const float*   x      = (const float*)d_in[0];
    const int32_t* pw     = (const int32_t*)d_in[1];
    const float*   scales = (const float*)d_in[2];
    const float*   bias   = (const float*)d_in[3];
    float*         out    = (float*)d_out;
    const int M = in_sizes[0] / KDIM;   // 8192

    const long long nx = (long long)M * KDIM;
    const int cv_blocks = (int)((nx / 8 + 255) / 256);
    prep_kernel<<<DQ_BLOCKS + cv_blocks, 256>>>(x, pw, scales, nx);

    const int smem_bytes = STAGES * (A_STG + B_STG) * (int)sizeof(__half);  // 107520
    cudaFuncSetAttribute(gemm_kernel, cudaFuncAttributeMaxDynamicSharedMemorySize,
                         smem_bytes);
    const int grid = (M / BM) * (NDIM / BN);   // 64*86 = 5504
    gemm_kernel<<<grid, 256, smem_bytes>>>(bias, out, M);
}

// round 14
// speedup vs baseline: 1.2193x; 1.2193x over previous
#include <cuda_runtime.h>
#include <cuda_fp16.h>
#include <cstdint>
#include <cstddef>

// Problem constants (fixed for this problem; M derived at launch)
#define KDIM 4096
#define NDIM 11008
#define MMAX 8192
#define BM 128
#define BN 256
#define BK 64
#define STAGES 4
#define KT (KDIM / BK)        // 64
#define SA_STRIDE 72          // 64+8 halves -> 144B row stride (conflict-free ldmatrix)
#define SB_STRIDE 264         // 256+8 halves -> 528B row stride
#define A_STG (BM * SA_STRIDE)
#define B_STG (BK * SB_STRIDE)
#define DQ_BLOCKS ((NDIM / 64) * (KDIM / 256))   // 172*16 = 2752

// fp16 scratch: dequantized weights (scale folded), K-major [K][N]; fp16 copy of x.
static __device__ __half g_W[(size_t)KDIM * NDIM];   // 90.2 MB
static __device__ __half g_X[(size_t)MMAX * KDIM];   // 67.1 MB

// ---------------------------------------------------------------------------
// Phase 1 (fused): blocks [0, DQ_BLOCKS) dequantize packed ternary -> g_W;
// blocks [DQ_BLOCKS, ...) convert x f32->f16 -> g_X.
// Dequant math (proven bit-identical): 16-entry half2 LUT of exact (code-1)
// in {-1,0,+1}; hmul2 by fp16 scale gives {-s,0,+s} exactly.
// ---------------------------------------------------------------------------
__global__ __launch_bounds__(256) void prep_kernel(
    const float* __restrict__ x, const int32_t* __restrict__ pw,
    const float* __restrict__ scales, long long nx)
{
    __shared__ __half2 lut[16];
    __shared__ __half sw[256][72];   // row stride 144B (16B-aligned)
    const int t = threadIdx.x;

    if (blockIdx.x >= DQ_BLOCKS) {
        long long i = ((long long)(blockIdx.x - DQ_BLOCKS) * 256 + t) * 8;
        if (i + 8 <= nx) {
            float4 a = *reinterpret_cast<const float4*>(x + i);
            float4 b = *reinterpret_cast<const float4*>(x + i + 4);
            __half2 h[4];
            h[0] = __floats2half2_rn(a.x, a.y);
            h[1] = __floats2half2_rn(a.z, a.w);
            h[2] = __floats2half2_rn(b.x, b.y);
            h[3] = __floats2half2_rn(b.z, b.w);
            *reinterpret_cast<uint4*>(&g_X[i]) = *reinterpret_cast<uint4*>(h);
        }
        return;
    }

    const int n0  = (blockIdx.x % (NDIM / 64)) * 64;
    const int kp0 = (blockIdx.x / (NDIM / 64)) * 16;
    const int nl  = (t & 31) * 2;
    const int r0  = t >> 5;

    if (t < 16)
        lut[t] = __halves2half2(__int2half_rn((t & 3) - 1),
                                __int2half_rn((t >> 2) - 1));
    __syncthreads();

#pragma unroll
    for (int rr = r0; rr < 16; rr += 8) {
        const int kp = kp0 + rr;
        const int n  = n0 + nl;
        const int2  vab = *reinterpret_cast<const int2*>(&pw[(size_t)kp * NDIM + n]);
        const uint32_t va = (uint32_t)vab.x;
        const uint32_t vb = (uint32_t)vab.y;
        const int g = kp >> 3;
        const float2 sf = *reinterpret_cast<const float2*>(&scales[(size_t)g * NDIM + n]);
        const __half2 s2 = __floats2half2_rn(sf.x, sf.y);

        const uint32_t w1 = (va & 0x33333333u) | ((vb & 0x33333333u) << 2);
        const uint32_t w2 = ((va >> 2) & 0x33333333u) | (((vb >> 2) & 0x33333333u) << 2);

        __half* row_base = &sw[rr * 16][0];
#pragma unroll
        for (int m = 0; m < 8; m++) {
            const __half2 he = __hmul2(lut[(w1 >> (4 * m)) & 0xFu], s2);
            const __half2 ho = __hmul2(lut[(w2 >> (4 * m)) & 0xFu], s2);
            *reinterpret_cast<__half2*>(row_base + (2 * m) * 72 + nl)     = he;
            *reinterpret_cast<__half2*>(row_base + (2 * m + 1) * 72 + nl) = ho;
        }
    }
    __syncthreads();

#pragma unroll
    for (int i = t; i < 2048; i += 256) {
        const int row = i >> 3, c = i & 7;
        *reinterpret_cast<uint4*>(&g_W[(size_t)(kp0 * 16 + row) * NDIM + n0 + c * 8]) =
            *reinterpret_cast<const uint4*>(&sw[row][c * 8]);
    }
}

// ---------------------------------------------------------------------------
// Phase 2: persistent fp16 GEMM, fp32 acc. R11 mainloop (128x256, 4 stages,
// double-buffered fragments) but one CTA per SM walks tiles with the cp.async
// pipeline running seamlessly ACROSS tile boundaries: the load cursor leads
// the compute cursor by STAGES-1 k-iterations, spilling into the next tile's
// k=0..2 while the current tile finishes. mma issued before the ks3 barrier.
// C_f32 = float( half(acc) + half(bias) ), reference rounding order.
// ---------------------------------------------------------------------------
#define CP_ASYNC16(dst, src) \
    asm volatile("cp.async.cg.shared.global [%0], [%1], 16;\n" :: "r"(dst), "l"(src))

__device__ __forceinline__ void tile_coords(int pid, int tiles_m, int tiles_n,
                                            int& m0, int& n0) {
    const int GROUPM = 16;
    const int per_group = GROUPM * tiles_n;
    const int gid = pid / per_group;
    const int first_m = gid * GROUPM;
    const int gsz = min(GROUPM, tiles_m - first_m);
    const int rr  = pid % per_group;
    m0 = (first_m + rr % gsz) * BM;
    n0 = (rr / gsz) * BN;
}

__global__ __launch_bounds__(256, 1) void gemm_kernel(
    const float* __restrict__ bias, float* __restrict__ C, int M)
{
    extern __shared__ __half smem[];
    __half* sA = smem;                      // [STAGES][BM][SA_STRIDE]
    __half* sB = smem + STAGES * A_STG;     // [STAGES][BK][SB_STRIDE]

    const int tiles_n = NDIM / BN;          // 43
    const int tiles_m = M / BM;             // 64
    const int NT = tiles_m * tiles_n;       // 2752
    const int step = gridDim.x;

    if ((int)blockIdx.x >= NT) return;
    const int nmine = (NT - 1 - (int)blockIdx.x) / step + 1;
    const int iters = nmine * KT;

    const int tid  = threadIdx.x;
    const int lane = tid & 31;
    const int warp = tid >> 5;
    const int wr = warp & 1;     // 0..1 -> 64-row slice
    const int wc = warp >> 1;    // 0..3 -> 64-col slice

    float acc[4][8][4];
#pragma unroll
    for (int a = 0; a < 4; a++)
#pragma unroll
        for (int b = 0; b < 8; b++)
#pragma unroll
            for (int c = 0; c < 4; c++) acc[a][b][c] = 0.f;

    const uint32_t sA_base = (uint32_t)__cvta_generic_to_shared(sA);
    const uint32_t sB_base = (uint32_t)__cvta_generic_to_shared(sB);

    // gmem->smem 16B-chunk coordinates.
    const int a_row = tid >> 3;           // +32/iter (4 iters)
    const int a_c   = (tid & 7) * 8;
    const int b_row = tid >> 5;           // +8/iter (4 iters x 2 halves)
    const int b_c   = (tid & 31) * 8;

    // Compute-tile cursor (for the epilogue) and load-tile cursor (for cp.async).
    int ctid = blockIdx.x, cm0, cn0;
    tile_coords(ctid, tiles_m, tiles_n, cm0, cn0);
    int ltid = ctid, lm0 = cm0, ln0 = cn0;
    const __half* lA = g_X + (size_t)(lm0 + a_row) * KDIM + a_c;
    const __half* lB = g_W + (size_t)b_row * NDIM + ln0 + b_c;

    auto load_A = [&](int stage, int kt) {
        uint32_t da = sA_base + (uint32_t)(stage * A_STG + a_row * SA_STRIDE + a_c) * 2;
        const __half* ga = lA + kt * BK;
#pragma unroll
        for (int i = 0; i < 4; i++) {
            CP_ASYNC16(da, ga);
            da += 32 * SA_STRIDE * 2;
            ga += (size_t)32 * KDIM;
        }
    };
    auto load_B = [&](int stage, int kt, int half) {
        uint32_t db = sB_base + (uint32_t)(stage * B_STG + (b_row + half * 32) * SB_STRIDE + b_c) * 2;
        const __half* gb = lB + (size_t)(kt * BK + half * 32) * NDIM;
#pragma unroll
        for (int i = 0; i < 4; i++) {
            CP_ASYNC16(db, gb);
            db += 8 * SB_STRIDE * 2;
            gb += (size_t)8 * NDIM;
        }
    };

    // ldmatrix lane-address components (R11-proven mapping).
    const int lrow  = (lane & 7) + ((lane >> 3) & 1) * 8;
    const int acoff = ((lane >> 4) & 1) * 8;
    const int bkr   = (lane & 7) + ((lane >> 3) & 1) * 8;
    const int bnc   = wc * 64 + ((lane >> 4) & 1) * 8;

    uint32_t fa[2][4][4], fb[2][8][2];

    auto ldsm = [&](int stage, int ks, int buf) {
        const uint32_t pa = sA_base + (uint32_t)(stage * A_STG) * 2;
        const uint32_t pb = sB_base + (uint32_t)(stage * B_STG) * 2;
#pragma unroll
        for (int mi = 0; mi < 4; mi++) {
            const uint32_t addr = pa +
                (uint32_t)((wr * 64 + mi * 16 + lrow) * SA_STRIDE + ks * 16 + acoff) * 2;
            asm volatile("ldmatrix.sync.aligned.m8n8.x4.shared.b16 {%0,%1,%2,%3}, [%4];\n"
                : "=r"(fa[buf][mi][0]), "=r"(fa[buf][mi][1]),
                  "=r"(fa[buf][mi][2]), "=r"(fa[buf][mi][3])
                : "r"(addr));
        }
#pragma unroll
        for (int ng = 0; ng < 4; ng++) {
            const uint32_t addr = pb +
                (uint32_t)((ks * 16 + bkr) * SB_STRIDE + bnc + ng * 16) * 2;
            uint32_t r0, r1, r2, r3;
            asm volatile("ldmatrix.sync.aligned.m8n8.x4.trans.shared.b16 {%0,%1,%2,%3}, [%4];\n"
                : "=r"(r0), "=r"(r1), "=r"(r2), "=r"(r3) : "r"(addr));
            fb[buf][2 * ng][0] = r0;     fb[buf][2 * ng][1] = r1;
            fb[buf][2 * ng + 1][0] = r2; fb[buf][2 * ng + 1][1] = r3;
        }
    };

    auto mma_all = [&](int buf) {
#pragma unroll
        for (int mi = 0; mi < 4; mi++)
#pragma unroll
            for (int ni = 0; ni < 8; ni++) {
                asm volatile(
                    "mma.sync.aligned.m16n8k16.row.col.f32.f16.f16.f32 "
                    "{%0,%1,%2,%3}, {%4,%5,%6,%7}, {%8,%9}, {%0,%1,%2,%3};\n"
                    : "+f"(acc[mi][ni][0]), "+f"(acc[mi][ni][1]),
                      "+f"(acc[mi][ni][2]), "+f"(acc[mi][ni][3])
                    : "r"(fa[buf][mi][0]), "r"(fa[buf][mi][1]),
                      "r"(fa[buf][mi][2]), "r"(fa[buf][mi][3]),
                      "r"(fb[buf][ni][0]), "r"(fb[buf][ni][1]));
            }
    };

    // Prologue: load iterations 0..2 (tile 0, kt 0..2), prime fragments.
#pragma unroll
    for (int s = 0; s < STAGES - 1; s++) {
        load_A(s, s);
        load_B(s, s, 0);
        load_B(s, s, 1);
        asm volatile("cp.async.commit_group;\n");
    }
    asm volatile("cp.async.wait_group %0;\n" :: "n"(STAGES - 2) : "memory");
    __syncthreads();
    ldsm(0, 0, 0);

    for (int ci = 0; ci < iters; ci++) {
        const int stage = ci & (STAGES - 1);
        const int li = ci + STAGES - 1;
        const bool do_load = li < iters;
        const int lstage = li & (STAGES - 1);
        const int lkt = li & (KT - 1);
#pragma unroll
        for (int ks = 0; ks < 4; ks++) {
            const int cur = ks & 1, nxt = cur ^ 1;
            if (ks == 0 && do_load) {
                if (lkt == 0 && li >= KT) {   // load cursor crosses into next tile
                    ltid += step;
                    tile_coords(ltid, tiles_m, tiles_n, lm0, ln0);
                    lA = g_X + (size_t)(lm0 + a_row) * KDIM + a_c;
                    lB = g_W + (size_t)b_row * NDIM + ln0 + b_c;
                }
                load_A(lstage, lkt);
            }
            if (ks == 1 && do_load) load_B(lstage, lkt, 0);
            if (ks == 2) {
                if (do_load) load_B(lstage, lkt, 1);
                asm volatile("cp.async.commit_group;\n");   // one group per ci
            }
            if (ks < 3) {
                ldsm(stage, ks + 1, nxt);
                mma_all(cur);
            } else {
                mma_all(cur);   // feed the pipe before the barrier
                asm volatile("cp.async.wait_group %0;\n" :: "n"(STAGES - 2) : "memory");
                __syncthreads();
                if (ci + 1 < iters) ldsm((ci + 1) & (STAGES - 1), 0, nxt);
            }
        }

        if ((ci & (KT - 1)) == KT - 1) {
            // Epilogue for the finished tile; loads for the next tile are in
            // flight and the tensor pipe drains queued MMAs meanwhile.
#pragma unroll
            for (int mi = 0; mi < 4; mi++) {
                const int row = cm0 + wr * 64 + mi * 16 + (lane >> 2);
#pragma unroll
                for (int ni = 0; ni < 8; ni++) {
                    const int col = cn0 + wc * 64 + ni * 8 + (lane & 3) * 2;
                    const float2 bf32 = *reinterpret_cast<const float2*>(bias + col);
                    const __half2 bv = __floats2half2_rn(bf32.x, bf32.y);
                    __half2 v0 = __hadd2(__floats2half2_rn(acc[mi][ni][0], acc[mi][ni][1]), bv);
                    __half2 v1 = __hadd2(__floats2half2_rn(acc[mi][ni][2], acc[mi][ni][3]), bv);
                    float2 o0 = __half22float2(v0);
                    float2 o1 = __half22float2(v1);
                    *reinterpret_cast<float2*>(C + (size_t)row * NDIM + col) = o0;
                    *reinterpret_cast<float2*>(C + (size_t)(row + 8) * NDIM + col) = o1;
#pragma unroll
                    for (int c = 0; c < 4; c++) acc[mi][ni][c] = 0.f;
                }
            }
            ctid += step;
            if (ctid < NT) tile_coords(ctid, tiles_m, tiles_n, cm0, cn0);
        }
    }
}

// ---------------------------------------------------------------------------
extern "C" void kernel_launch(void* const* d_in, const int* in_sizes, int n_in,
                              void* d_out, int out_size) {
    const float*   x      = (const float*)d_in[0];
    const int32_t* pw     = (const int32_t*)d_in[1];
    const float*   scales = (const float*)d_in[2];
    const float*   bias   = (const float*)d_in[3];
    float*         out    = (float*)d_out;
    const int M = in_sizes[0] / KDIM;   // 8192

    const long long nx = (long long)M * KDIM;
    const int cv_blocks = (int)((nx / 8 + 255) / 256);
    prep_kernel<<<DQ_BLOCKS + cv_blocks, 256>>>(x, pw, scales, nx);

    int sm_count = 148;
    cudaDeviceGetAttribute(&sm_count, cudaDevAttrMultiProcessorCount, 0);
    const int NT = (M / BM) * (NDIM / BN);   // 2752
    const int grid = (sm_count < NT) ? sm_count : NT;

    const int smem_bytes = STAGES * (A_STG + B_STG) * (int)sizeof(__half);  // 208896
    cudaFuncSetAttribute(gemm_kernel, cudaFuncAttributeMaxDynamicSharedMemorySize,
                         smem_bytes);
    gemm_kernel<<<grid, 256, smem_bytes>>>(bias, out, M);
}